// round 1
// baseline (speedup 1.0000x reference)
#include <cuda_runtime.h>

#define N_NODES 50000
#define E_EDGES 800000
#define TOT_E   (E_EDGES + N_NODES)   // 850000, incl. self-loops
#define HID     32
#define HEADS   4
#define F1      (HEADS * HID)          // 128
#define NEG_SLOPE 0.2f

// ---- scratch (device globals; no allocation allowed) ----
__device__ __align__(16) float g_h1[N_NODES * F1];      // layer1 transformed feats
__device__ __align__(16) float g_asrc1[N_NODES * HEADS];
__device__ __align__(16) float g_adst1[N_NODES * HEADS];
__device__ __align__(16) float g_out1[N_NODES * F1];    // unnormalized numerator
__device__ __align__(16) float g_den1[N_NODES * HEADS]; // softmax denominator
__device__ __align__(16) float g_h2[N_NODES * HID];     // layer2 transformed feats
__device__ __align__(16) float g_asrc2[N_NODES];
__device__ __align__(16) float g_adst2[N_NODES];
__device__ __align__(16) float g_out2[N_NODES * HID];
__device__ __align__(16) float g_den2[N_NODES];

__device__ __forceinline__ float warp_sum(float v) {
#pragma unroll
    for (int o = 16; o; o >>= 1) v += __shfl_xor_sync(0xffffffffu, v, o);
    return v;
}

__device__ __forceinline__ float lrelu(float e) { return e > 0.f ? e : NEG_SLOPE * e; }
__device__ __forceinline__ float elu(float v)   { return v > 0.f ? v : __expf(v) - 1.f; }

// ============================================================================
// K1: h1 = x @ W1 ([N,5]@[5,128]); a_src1/a_dst1 per head; zero ALL accumulators
// (must re-zero every launch: graph replays reuse the same device globals).
// One block (128 threads) per node.
// ============================================================================
__global__ void k1_node1(const float* __restrict__ x, const float* __restrict__ W1,
                         const float* __restrict__ as1, const float* __restrict__ ad1) {
    int n = blockIdx.x;
    int t = threadIdx.x;                 // 0..127 = output feature
    __shared__ float sx[5];
    __shared__ float sW[5 * F1];
    if (t < 5) sx[t] = x[n * 5 + t];
#pragma unroll
    for (int k = 0; k < 5; k++) sW[k * F1 + t] = W1[k * F1 + t];
    __syncthreads();

    float h = 0.f;
#pragma unroll
    for (int k = 0; k < 5; k++) h = fmaf(sx[k], sW[k * F1 + t], h);
    g_h1[n * F1 + t]  = h;
    g_out1[n * F1 + t] = 0.f;

    int head = t >> 5, lane = t & 31;
    float ps = warp_sum(h * as1[head * HID + lane]);
    float pd = warp_sum(h * ad1[head * HID + lane]);
    if (lane == 0) {
        g_asrc1[n * HEADS + head] = ps;
        g_adst1[n * HEADS + head] = pd;
        g_den1 [n * HEADS + head] = 0.f;
    }
    if (t < HID) g_out2[n * HID + t] = 0.f;
    if (t == 0)  g_den2[n] = 0.f;
}

// ============================================================================
// K2: layer-1 edge pass. One warp per edge. Unnormalized softmax accumulation:
//   w[h] = exp(leaky_relu(a_src[src][h] + a_dst[dst][h]))
//   out1[dst] += w[h] * h1[src];  den1[dst][h] += w[h]
// (segment_max dropped: logits are O(0.1), exp is numerically safe; softmax is
//  shift-invariant so the result is mathematically identical.)
// ============================================================================
__global__ void k2_edge1(const int* __restrict__ ei) {
    int w = (blockIdx.x * blockDim.x + threadIdx.x) >> 5;
    if (w >= TOT_E) return;
    int lane = threadIdx.x & 31;

    int src, dst;
    if (w < E_EDGES) { src = ei[w]; dst = ei[E_EDGES + w]; }
    else             { src = dst = w - E_EDGES; }

    float4 as = *reinterpret_cast<const float4*>(&g_asrc1[src * 4]);
    float4 ad = *reinterpret_cast<const float4*>(&g_adst1[dst * 4]);
    float w0 = __expf(lrelu(as.x + ad.x));
    float w1 = __expf(lrelu(as.y + ad.y));
    float w2 = __expf(lrelu(as.z + ad.z));
    float w3 = __expf(lrelu(as.w + ad.w));

    if (lane < 4) {
        float wv = (lane == 0) ? w0 : (lane == 1) ? w1 : (lane == 2) ? w2 : w3;
        atomicAdd(&g_den1[dst * 4 + lane], wv);
    }

    const float* hs = &g_h1[src * F1];
    float*       od = &g_out1[dst * F1];
    atomicAdd(&od[lane],      w0 * hs[lane]);
    atomicAdd(&od[32 + lane], w1 * hs[32 + lane]);
    atomicAdd(&od[64 + lane], w2 * hs[64 + lane]);
    atomicAdd(&od[96 + lane], w3 * hs[96 + lane]);
}

// ============================================================================
// K3: normalize layer-1 output, +b1, ELU; then h2 = h1out @ W2 ([128]@[128,32]);
// a_src2/a_dst2. 8 nodes per 256-thread block (one warp per node), W2 in smem.
// ============================================================================
__global__ void k3_node2(const float* __restrict__ b1, const float* __restrict__ W2,
                         const float* __restrict__ as2, const float* __restrict__ ad2) {
    __shared__ float sW2[F1 * HID];     // 16 KB
    __shared__ float sH[8][F1];         // 4 KB
    int t = threadIdx.x;
    for (int i = t; i < F1 * HID; i += 256) sW2[i] = W2[i];
    __syncthreads();

    int wid = t >> 5, lane = t & 31;
    int n = blockIdx.x * 8 + wid;
    if (n >= N_NODES) return;

#pragma unroll
    for (int h = 0; h < HEADS; h++) {
        int k = h * 32 + lane;
        float den = g_den1[n * HEADS + h];
        float v = g_out1[n * F1 + k] / den + b1[k];
        sH[wid][k] = elu(v);
    }
    __syncwarp();

    float acc = 0.f;
#pragma unroll 8
    for (int k = 0; k < F1; k++) acc = fmaf(sH[wid][k], sW2[k * HID + lane], acc);
    g_h2[n * HID + lane] = acc;

    float ps = warp_sum(acc * as2[lane]);
    float pd = warp_sum(acc * ad2[lane]);
    if (lane == 0) { g_asrc2[n] = ps; g_adst2[n] = pd; }
}

// ============================================================================
// K4: layer-2 edge pass (1 head, 32 features). One warp per edge.
// ============================================================================
__global__ void k4_edge2(const int* __restrict__ ei) {
    int w = (blockIdx.x * blockDim.x + threadIdx.x) >> 5;
    if (w >= TOT_E) return;
    int lane = threadIdx.x & 31;

    int src, dst;
    if (w < E_EDGES) { src = ei[w]; dst = ei[E_EDGES + w]; }
    else             { src = dst = w - E_EDGES; }

    float wv = __expf(lrelu(g_asrc2[src] + g_adst2[dst]));
    if (lane == 0) atomicAdd(&g_den2[dst], wv);
    atomicAdd(&g_out2[dst * HID + lane], wv * g_h2[src * HID + lane]);
}

// ============================================================================
// K5: normalize, +b2, ELU; MLP head relu(v@Wc1+bc1)@Wc2+bc2. 1 thread/node.
// Weight reads are lane-uniform -> served by const/L1 broadcast.
// ============================================================================
__global__ void k5_head(const float* __restrict__ b2,  const float* __restrict__ Wc1,
                        const float* __restrict__ bc1, const float* __restrict__ Wc2,
                        const float* __restrict__ bc2, float* __restrict__ out) {
    int n = blockIdx.x * blockDim.x + threadIdx.x;
    if (n >= N_NODES) return;

    float inv_den = 1.f / g_den2[n];
    float t16[16];
#pragma unroll
    for (int j = 0; j < 16; j++) t16[j] = bc1[j];

#pragma unroll
    for (int c = 0; c < HID; c++) {
        float v = elu(g_out2[n * HID + c] * inv_den + b2[c]);
#pragma unroll
        for (int j = 0; j < 16; j++) t16[j] = fmaf(v, Wc1[c * 16 + j], t16[j]);
    }

    float acc = bc2[0];
#pragma unroll
    for (int j = 0; j < 16; j++) {
        float tv = t16[j] > 0.f ? t16[j] : 0.f;
        acc = fmaf(tv, Wc2[j], acc);
    }
    out[n] = acc;
}

// ============================================================================
extern "C" void kernel_launch(void* const* d_in, const int* in_sizes, int n_in,
                              void* d_out, int out_size) {
    const float* x   = (const float*)d_in[0];
    const int*   ei  = (const int*)  d_in[1];
    const float* W1  = (const float*)d_in[2];
    const float* as1 = (const float*)d_in[3];
    const float* ad1 = (const float*)d_in[4];
    const float* b1  = (const float*)d_in[5];
    const float* W2  = (const float*)d_in[6];
    const float* as2 = (const float*)d_in[7];
    const float* ad2 = (const float*)d_in[8];
    const float* b2  = (const float*)d_in[9];
    const float* Wc1 = (const float*)d_in[10];
    const float* bc1 = (const float*)d_in[11];
    const float* Wc2 = (const float*)d_in[12];
    const float* bc2 = (const float*)d_in[13];
    float* out = (float*)d_out;

    k1_node1<<<N_NODES, 128>>>(x, W1, as1, ad1);
    k2_edge1<<<(TOT_E + 7) / 8, 256>>>(ei);            // 8 warps/block, 1 edge/warp
    k3_node2<<<(N_NODES + 7) / 8, 256>>>(b1, W2, as2, ad2);
    k4_edge2<<<(TOT_E + 7) / 8, 256>>>(ei);
    k5_head<<<(N_NODES + 255) / 256, 256>>>(b2, Wc1, bc1, Wc2, bc2, out);
}

// round 3
// speedup vs baseline: 1.9603x; 1.9603x over previous
#include <cuda_runtime.h>

#define N_NODES 50000
#define E_EDGES 800000
#define TOT_E   (E_EDGES + N_NODES)   // 850000, incl. self-loops
#define HID     32
#define HEADS   4
#define F1      (HEADS * HID)          // 128
#define NEG_SLOPE 0.2f

#define SCAN_CHUNK 512
#define NB_SCAN    ((N_NODES + SCAN_CHUNK - 1) / SCAN_CHUNK)   // 98

// ---- scratch (device globals; no allocation allowed) ----
__device__ int   g_cnt[N_NODES];            // per-dst degree (incl. self-loop)
__device__ int   g_off[N_NODES];            // exclusive prefix (CSR row start)
__device__ int   g_cur[N_NODES];            // scatter cursors
__device__ int   g_bsum[NB_SCAN];           // scan partials
__device__ int   g_boff[NB_SCAN];
__device__ int   g_csr[TOT_E];              // src ids grouped by dst
__device__ __align__(16) float g_h1[N_NODES * F1];
__device__ __align__(16) float g_as1[N_NODES * HEADS];
__device__ __align__(16) float g_ad1[N_NODES * HEADS];
__device__ __align__(16) float g_out1[N_NODES * F1];   // post-softmax, post-ELU
__device__ __align__(16) float g_h2[N_NODES * HID];
__device__ float g_as2[N_NODES];
__device__ float g_ad2[N_NODES];

__device__ __forceinline__ float warp_sum_f(float v) {
#pragma unroll
    for (int o = 16; o; o >>= 1) v += __shfl_xor_sync(0xffffffffu, v, o);
    return v;
}
__device__ __forceinline__ int warp_sum_i(int v) {
#pragma unroll
    for (int o = 16; o; o >>= 1) v += __shfl_xor_sync(0xffffffffu, v, o);
    return v;
}
__device__ __forceinline__ float lrelu(float e) { return e > 0.f ? e : NEG_SLOPE * e; }
__device__ __forceinline__ float elu(float v)   { return v > 0.f ? v : __expf(v) - 1.f; }

// ============================================================================
// CSR construction (rebuilt every launch; int atomics only — cheap)
// ============================================================================
__global__ void kZ() {                              // zero degree counters
    int i = blockIdx.x * blockDim.x + threadIdx.x;
    if (i < N_NODES) g_cnt[i] = 0;
}

__global__ void kH(const int* __restrict__ ei) {    // histogram by dst
    int e = blockIdx.x * blockDim.x + threadIdx.x;
    if (e >= TOT_E) return;
    int dst = (e < E_EDGES) ? ei[E_EDGES + e] : (e - E_EDGES);
    atomicAdd(&g_cnt[dst], 1);
}

__global__ void kS1() {                             // per-chunk sums
    __shared__ int ws[SCAN_CHUNK / 32];
    int t = threadIdx.x, b = blockIdx.x;
    int i = b * SCAN_CHUNK + t;
    int x = (i < N_NODES) ? g_cnt[i] : 0;
    x = warp_sum_i(x);                              // all 32 lanes participate
    if ((t & 31) == 0) ws[t >> 5] = x;
    __syncthreads();
    if (t == 0) {
        int tot = 0;
#pragma unroll
        for (int w = 0; w < SCAN_CHUNK / 32; w++) tot += ws[w];
        g_bsum[b] = tot;
    }
}

__global__ void kS2() {                             // exclusive scan of 98 partials (serial)
    if (threadIdx.x == 0) {
        int run = 0;
        for (int b = 0; b < NB_SCAN; b++) { g_boff[b] = run; run += g_bsum[b]; }
    }
}

__global__ void kS3() {                             // chunk-local exclusive scan + base
    __shared__ int ws[SCAN_CHUNK / 32 + 1];
    int t = threadIdx.x, b = blockIdx.x;
    int i = b * SCAN_CHUNK + t;
    int lane = t & 31, wid = t >> 5;
    int v = (i < N_NODES) ? g_cnt[i] : 0;
    int x = v;
#pragma unroll
    for (int o = 1; o < 32; o <<= 1) {              // inclusive warp scan (all lanes)
        int y = __shfl_up_sync(0xffffffffu, x, o);
        if (lane >= o) x += y;
    }
    if (lane == 31) ws[wid + 1] = x;                // warp totals
    __syncthreads();
    if (t == 0) {                                   // serial scan of 16 warp totals
        ws[0] = 0;
        for (int w = 1; w < SCAN_CHUNK / 32; w++) ws[w] += ws[w - 1];
    }
    __syncthreads();
    int excl = x - v + ws[wid] + g_boff[b];
    if (i < N_NODES) { g_off[i] = excl; g_cur[i] = excl; }
}

__global__ void kC(const int* __restrict__ ei) {    // scatter src ids by dst
    int e = blockIdx.x * blockDim.x + threadIdx.x;
    if (e >= TOT_E) return;
    int src, dst;
    if (e < E_EDGES) { src = ei[e]; dst = ei[E_EDGES + e]; }
    else             { src = dst = e - E_EDGES; }
    int p = atomicAdd(&g_cur[dst], 1);
    g_csr[p] = src;
}

// ============================================================================
// K1: h1 = x @ W1; attention scalars via a = x·(W1@attᵀ)  (no warp reductions).
// 128 threads, 32 nodes per block; W1 (2.5KB) loaded to smem once per block.
// ============================================================================
__global__ void k1_node1(const float* __restrict__ x,  const float* __restrict__ W1,
                         const float* __restrict__ as1, const float* __restrict__ ad1) {
    __shared__ float sW[5 * F1];
    __shared__ float sva[5 * HEADS], svb[5 * HEADS];   // folded attention weights
    int t = threadIdx.x;
    for (int i = t; i < 5 * F1; i += 128) sW[i] = W1[i];
    if (t < 5 * HEADS) {
        int k = t / HEADS, h = t % HEADS;
        float s = 0.f, d = 0.f;
        for (int c = 0; c < HID; c++) {
            float w = W1[k * F1 + h * HID + c];
            s = fmaf(w, as1[h * HID + c], s);
            d = fmaf(w, ad1[h * HID + c], d);
        }
        sva[t] = s; svb[t] = d;
    }
    __syncthreads();

    int n0 = blockIdx.x * 32;
    for (int j = 0; j < 32; j++) {
        int n = n0 + j;
        if (n >= N_NODES) return;
        float xv[5];
#pragma unroll
        for (int k = 0; k < 5; k++) xv[k] = x[n * 5 + k];
        float h = 0.f;
#pragma unroll
        for (int k = 0; k < 5; k++) h = fmaf(xv[k], sW[k * F1 + t], h);
        g_h1[n * F1 + t] = h;
        if (t < HEADS) {
            float s = 0.f, d = 0.f;
#pragma unroll
            for (int k = 0; k < 5; k++) {
                s = fmaf(xv[k], sva[k * HEADS + t], s);
                d = fmaf(xv[k], svb[k * HEADS + t], d);
            }
            g_as1[n * HEADS + t] = s;
            g_ad1[n * HEADS + t] = d;
        }
    }
}

// ============================================================================
// KG1: layer-1 gather. One warp per dst node; lane owns features [4l,4l+3]
// (float4), head = lane>>3. Softmax denom accumulates in-register; output is
// normalized + bias + ELU — final layer-1 features, written once. No atomics.
// ============================================================================
__global__ void kG1(const float* __restrict__ b1) {
    int n = (blockIdx.x * blockDim.x + threadIdx.x) >> 5;
    if (n >= N_NODES) return;
    int lane = threadIdx.x & 31;
    int head = lane >> 3;

    float adv = g_ad1[n * HEADS + head];
    int beg = g_off[n], cnt = g_cnt[n];

    float a0 = 0.f, a1 = 0.f, a2 = 0.f, a3 = 0.f, den = 0.f;
    int src = g_csr[beg];
    for (int j = 0; j < cnt; j++) {
        int nsrc = (j + 1 < cnt) ? g_csr[beg + j + 1] : 0;
        float as = g_as1[src * HEADS + head];
        float w  = __expf(lrelu(as + adv));
        float4 hv = *reinterpret_cast<const float4*>(&g_h1[src * F1 + lane * 4]);
        a0 = fmaf(w, hv.x, a0);
        a1 = fmaf(w, hv.y, a1);
        a2 = fmaf(w, hv.z, a2);
        a3 = fmaf(w, hv.w, a3);
        den += w;
        src = nsrc;
    }
    float inv = 1.f / den;
    int f = lane * 4;
    float4 bv = *reinterpret_cast<const float4*>(&b1[f]);
    float4 o;
    o.x = elu(fmaf(a0, inv, bv.x));
    o.y = elu(fmaf(a1, inv, bv.y));
    o.z = elu(fmaf(a2, inv, bv.z));
    o.w = elu(fmaf(a3, inv, bv.w));
    *reinterpret_cast<float4*>(&g_out1[n * F1 + f]) = o;
}

// ============================================================================
// K3: h2 = out1 @ W2 ([128]@[128,32]) + attention scalars. 8 nodes/block,
// W2 (16KB) in smem.
// ============================================================================
__global__ void k3_node2(const float* __restrict__ W2,
                         const float* __restrict__ as2, const float* __restrict__ ad2) {
    __shared__ float sW2[F1 * HID];
    __shared__ float sH[8][F1];
    int t = threadIdx.x;
    for (int i = t; i < F1 * HID; i += 256) sW2[i] = W2[i];
    __syncthreads();

    int wid = t >> 5, lane = t & 31;
    int n = blockIdx.x * 8 + wid;
    if (n >= N_NODES) return;

    float4 hv = *reinterpret_cast<const float4*>(&g_out1[n * F1 + lane * 4]);
    sH[wid][lane * 4 + 0] = hv.x;
    sH[wid][lane * 4 + 1] = hv.y;
    sH[wid][lane * 4 + 2] = hv.z;
    sH[wid][lane * 4 + 3] = hv.w;
    __syncwarp();

    float acc = 0.f;
#pragma unroll 8
    for (int k = 0; k < F1; k++) acc = fmaf(sH[wid][k], sW2[k * HID + lane], acc);
    g_h2[n * HID + lane] = acc;

    float ps = warp_sum_f(acc * as2[lane]);
    float pd = warp_sum_f(acc * ad2[lane]);
    if (lane == 0) { g_as2[n] = ps; g_ad2[n] = pd; }
}

// ============================================================================
// KG2: layer-2 gather (1 head, 32 feats) + fused MLP head. One warp per node.
// v = elu(softmax-agg + b2); out = relu(v@Wc1+bc1)@Wc2+bc2. No atomics.
// ============================================================================
__global__ void kG2(const float* __restrict__ b2,  const float* __restrict__ Wc1,
                    const float* __restrict__ bc1, const float* __restrict__ Wc2,
                    const float* __restrict__ bc2, float* __restrict__ out) {
    __shared__ float sv[8][HID];
    int n = (blockIdx.x * blockDim.x + threadIdx.x) >> 5;
    if (n >= N_NODES) return;
    int lane = threadIdx.x & 31;
    int wid = (threadIdx.x >> 5) & 7;

    float adv = g_ad2[n];
    int beg = g_off[n], cnt = g_cnt[n];

    float acc = 0.f, den = 0.f;
    int src = g_csr[beg];
    for (int j = 0; j < cnt; j++) {
        int nsrc = (j + 1 < cnt) ? g_csr[beg + j + 1] : 0;
        float w = __expf(lrelu(g_as2[src] + adv));
        float h = g_h2[src * HID + lane];
        acc = fmaf(w, h, acc);
        den += w;
        src = nsrc;
    }
    float v = elu(acc / den + b2[lane]);
    sv[wid][lane] = v;
    __syncwarp();

    float tj = 0.f;
    if (lane < 16) {
        tj = bc1[lane];
#pragma unroll
        for (int c = 0; c < HID; c++) tj = fmaf(sv[wid][c], Wc1[c * 16 + lane], tj);
        tj = fmaxf(tj, 0.f) * Wc2[lane];
    }
#pragma unroll
    for (int o = 16; o; o >>= 1) tj += __shfl_xor_sync(0xffffffffu, tj, o);  // all lanes
    if (lane == 0) out[n] = tj + bc2[0];
}

// ============================================================================
extern "C" void kernel_launch(void* const* d_in, const int* in_sizes, int n_in,
                              void* d_out, int out_size) {
    const float* x   = (const float*)d_in[0];
    const int*   ei  = (const int*)  d_in[1];
    const float* W1  = (const float*)d_in[2];
    const float* as1 = (const float*)d_in[3];
    const float* ad1 = (const float*)d_in[4];
    const float* b1  = (const float*)d_in[5];
    const float* W2  = (const float*)d_in[6];
    const float* as2 = (const float*)d_in[7];
    const float* ad2 = (const float*)d_in[8];
    const float* b2  = (const float*)d_in[9];
    const float* Wc1 = (const float*)d_in[10];
    const float* bc1 = (const float*)d_in[11];
    const float* Wc2 = (const float*)d_in[12];
    const float* bc2 = (const float*)d_in[13];
    float* out = (float*)d_out;

    // CSR build
    kZ <<<(N_NODES + 255) / 256, 256>>>();
    kH <<<(TOT_E + 255) / 256, 256>>>(ei);
    kS1<<<NB_SCAN, SCAN_CHUNK>>>();
    kS2<<<1, 32>>>();
    kS3<<<NB_SCAN, SCAN_CHUNK>>>();
    kC <<<(TOT_E + 255) / 256, 256>>>(ei);

    // dense node transform (independent of CSR)
    k1_node1<<<(N_NODES + 31) / 32, 128>>>(x, W1, as1, ad1);

    // layer 1 gather -> layer 2 transform -> layer 2 gather + head
    kG1<<<(N_NODES * 32 + 255) / 256, 256>>>(b1);
    k3_node2<<<(N_NODES + 7) / 8, 256>>>(W2, as2, ad2);
    kG2<<<(N_NODES * 32 + 255) / 256, 256>>>(b2, Wc1, bc1, Wc2, bc2, out);
}